// round 11
// baseline (speedup 1.0000x reference)
#include <cuda_runtime.h>
#include <cuda_bf16.h>

// Rows = 4194304, 16 fp32/row (64B), out = rows x 3 fp32 one-hot.
// selected = (f11 > 0.5) ? 0 : ((f4+f5 > f6+f7) ? 1 : 2)
//
// Converged shape: fully-coalesced .cs input stream, warp-ballot predicate
// exchange, all-lane .cs scalar stores (3 x contiguous 128B warp spans).
// R11 probe: CTA granularity 256->128 threads (grid 16384) — smaller
// per-CTA LDG bursts (less cross-CTA L1tex-queue contention) and finer
// work-steal balance. Everything else identical to R10 (the best so far).

#define NITER 2    // 128 rows per block-iter -> 256 rows per block

__global__ __launch_bounds__(128)
void gating_kernel(const float4* __restrict__ in,
                   float* __restrict__ out,
                   int n_rows)
{
    const unsigned FULL = 0xffffffffu;
    int lane = threadIdx.x & 31;
    int warp = threadIdx.x >> 5;           // 0..3

    long long block_row0 = (long long)blockIdx.x * (128 * NITER);

    // Hoisted per-lane store constants: store j (j=0,1,2) writes output
    // float g_j = 32*j + lane of the warp's 96-float tile.
    int g0 = lane, g1 = lane + 32, g2 = lane + 64;
    int r0 = g0 / 3, r1 = g1 / 3, r2 = g2 / 3;
    int c0 = g0 - 3 * r0, c1 = g1 - 3 * r1, c2 = g2 - 3 * r2;
    int ch0 = r0 >> 3, ch1 = r1 >> 3, ch2 = r2 >> 3;
    int se0 = (r0 & 7) * 4, se1 = (r1 & 7) * 4, se2 = (r2 & 7) * 4;

#pragma unroll
    for (int it = 0; it < NITER; it++) {
        long long row_w = block_row0 + it * 128 + warp * 32;   // warp's 32 rows
        const float4* src = in + row_w * 4;

        // 4 contiguous LDG.128.CS per lane; 512B warp-contiguous each.
        float4 v0 = __ldcs(&src[lane]);
        float4 v1 = __ldcs(&src[lane + 32]);
        float4 v2 = __ldcs(&src[lane + 64]);
        float4 v3 = __ldcs(&src[lane + 96]);

        unsigned m[8];
        m[0] = __ballot_sync(FULL, v0.w > 0.5f);               // e0, chunk 0
        m[1] = __ballot_sync(FULL, v0.x + v0.y > v0.z + v0.w); // cmp, chunk 0
        m[2] = __ballot_sync(FULL, v1.w > 0.5f);
        m[3] = __ballot_sync(FULL, v1.x + v1.y > v1.z + v1.w);
        m[4] = __ballot_sync(FULL, v2.w > 0.5f);
        m[5] = __ballot_sync(FULL, v2.x + v2.y > v2.z + v2.w);
        m[6] = __ballot_sync(FULL, v3.w > 0.5f);
        m[7] = __ballot_sync(FULL, v3.x + v3.y > v3.z + v3.w);

        // Row r's predicates sit at bit (4*(r&7)+2) (e0) / +1 (cmp) of its
        // chunk's ballot masks (row r's data lived in lanes 4r+1 / 4r+2).
        auto val = [&](int ch, int se, int c) -> float {
            unsigned me = (ch & 2) ? ((ch & 1) ? m[6] : m[4])
                                   : ((ch & 1) ? m[2] : m[0]);
            unsigned mc = (ch & 2) ? ((ch & 1) ? m[7] : m[5])
                                   : ((ch & 1) ? m[3] : m[1]);
            bool e0 = (me >> (se + 2)) & 1;
            bool cm = (mc >> (se + 1)) & 1;
            int sel = e0 ? 0 : (cm ? 1 : 2);
            return (sel == c) ? 1.0f : 0.0f;
        };

        // 96 floats per warp tile; 3 stores, each a contiguous 128B warp span.
        float* dst = out + row_w * 3;
        __stcs(&dst[g0], val(ch0, se0, c0));
        __stcs(&dst[g1], val(ch1, se1, c1));
        __stcs(&dst[g2], val(ch2, se2, c2));
    }
}

extern "C" void kernel_launch(void* const* d_in, const int* in_sizes, int n_in,
                              void* d_out, int out_size)
{
    const float* features = (const float*)d_in[0];
    float* out = (float*)d_out;
    int n_rows = in_sizes[0] / 16;                  // 4194304

    int rows_per_block = 128 * NITER;               // 256
    int grid = n_rows / rows_per_block;             // 16384 (exact)
    gating_kernel<<<grid, 128>>>((const float4*)features, out, n_rows);
}

// round 12
// speedup vs baseline: 1.1008x; 1.1008x over previous
#include <cuda_runtime.h>
#include <cuda_bf16.h>

// Rows = 4194304, 16 fp32/row (64B), out = rows x 3 fp32 one-hot.
// selected = (f11 > 0.5) ? 0 : ((f4+f5 > f6+f7) ? 1 : 2)
//
// Converged shape: fully-coalesced .cs input stream, warp-ballot predicate
// exchange, all-lane .cs scalar stores (3 x contiguous 128B warp spans).
// Granularity gradient has been monotone (grid 8192@256 -> 16384@128:
// 46.5 -> 44.6 us kernel). R12: finest step — NITER=1, one 128-row tile
// per 128-thread CTA, grid 32768. No iteration loop at all.

__global__ __launch_bounds__(128)
void gating_kernel(const float4* __restrict__ in,
                   float* __restrict__ out)
{
    const unsigned FULL = 0xffffffffu;
    int lane = threadIdx.x & 31;
    int warp = threadIdx.x >> 5;           // 0..3

    // Per-lane store constants: store j (j=0,1,2) writes output float
    // g_j = 32*j + lane of the warp's 96-float tile; row = g/3, col = g%3.
    int g0 = lane, g1 = lane + 32, g2 = lane + 64;
    int r0 = g0 / 3, r1 = g1 / 3, r2 = g2 / 3;
    int c0 = g0 - 3 * r0, c1 = g1 - 3 * r1, c2 = g2 - 3 * r2;
    int ch0 = r0 >> 3, ch1 = r1 >> 3, ch2 = r2 >> 3;
    int se0 = (r0 & 7) * 4, se1 = (r1 & 7) * 4, se2 = (r2 & 7) * 4;

    long long row_w = (long long)blockIdx.x * 128 + warp * 32;  // warp's 32 rows
    const float4* src = in + row_w * 4;

    // 4 contiguous LDG.128.CS per lane; 512B warp-contiguous each.
    float4 v0 = __ldcs(&src[lane]);
    float4 v1 = __ldcs(&src[lane + 32]);
    float4 v2 = __ldcs(&src[lane + 64]);
    float4 v3 = __ldcs(&src[lane + 96]);

    unsigned m[8];
    m[0] = __ballot_sync(FULL, v0.w > 0.5f);               // e0, chunk 0
    m[1] = __ballot_sync(FULL, v0.x + v0.y > v0.z + v0.w); // cmp, chunk 0
    m[2] = __ballot_sync(FULL, v1.w > 0.5f);
    m[3] = __ballot_sync(FULL, v1.x + v1.y > v1.z + v1.w);
    m[4] = __ballot_sync(FULL, v2.w > 0.5f);
    m[5] = __ballot_sync(FULL, v2.x + v2.y > v2.z + v2.w);
    m[6] = __ballot_sync(FULL, v3.w > 0.5f);
    m[7] = __ballot_sync(FULL, v3.x + v3.y > v3.z + v3.w);

    // Row r's predicates sit at bit (4*(r&7)+2) (e0) / +1 (cmp) of its
    // chunk's masks (row r's data lived in lanes 4r+1 / 4r+2).
    auto val = [&](int ch, int se, int c) -> float {
        unsigned me = (ch & 2) ? ((ch & 1) ? m[6] : m[4])
                               : ((ch & 1) ? m[2] : m[0]);
        unsigned mc = (ch & 2) ? ((ch & 1) ? m[7] : m[5])
                               : ((ch & 1) ? m[3] : m[1]);
        bool e0 = (me >> (se + 2)) & 1;
        bool cm = (mc >> (se + 1)) & 1;
        int sel = e0 ? 0 : (cm ? 1 : 2);
        return (sel == c) ? 1.0f : 0.0f;
    };

    // 96 floats per warp tile; 3 stores, each a contiguous 128B warp span.
    float* dst = out + row_w * 3;
    __stcs(&dst[g0], val(ch0, se0, c0));
    __stcs(&dst[g1], val(ch1, se1, c1));
    __stcs(&dst[g2], val(ch2, se2, c2));
}

extern "C" void kernel_launch(void* const* d_in, const int* in_sizes, int n_in,
                              void* d_out, int out_size)
{
    const float* features = (const float*)d_in[0];
    float* out = (float*)d_out;
    int n_rows = in_sizes[0] / 16;          // 4194304

    int grid = n_rows / 128;                // 32768 (exact)
    gating_kernel<<<grid, 128>>>((const float4*)features, out);
}